// round 11
// baseline (speedup 1.0000x reference)
#include <cuda_runtime.h>
#include <cstdint>

typedef unsigned long long u64;
typedef unsigned int u32;

#define N_EMBED   1024
#define EMBED_DIM 256
#define N_ROWS    65536
#define MTILE     128
#define NCHUNK    128
#define ZQ_ELEMS  (N_ROWS * EMBED_DIM)

// ---- global scratch: fragment-major pre-split operands ----
// A (z):  [mtile(4096)][kstep(32)][lane(32)*4regs]
// B (emb):[kstep(32)][ntile(128)][lane(32)*2regs]
__device__ float g_zh[16777216];
__device__ float g_zl[16777216];
__device__ float g_eh[262144];
__device__ float g_el[262144];
__device__ float g_e2[N_EMBED];

// ---- smem layout (bytes): 3-stage ring, 64KB per stage ----
// stage: AH 16K | AL 16K | BH 16K | BL 16K
#define STG(s)    ((s) * 65536)
#define AH_OFF(s) (STG(s) + 0)
#define AL_OFF(s) (STG(s) + 16384)
#define BH_OFF(s) (STG(s) + 32768)
#define BL_OFF(s) (STG(s) + 49152)
#define E2_OFF    196608
#define KEY_OFF   200704   /* 128 rows * 4 warp_n * 8B = 4KB */
#define SMEM_TOTAL 204800

__device__ __forceinline__ u32 cvt_tf32(float x) {
    u32 r;
    asm("cvt.rna.tf32.f32 %0, %1;" : "=r"(r) : "f"(x));
    return r;
}
__device__ __forceinline__ void split1(float x, float& hi, float& lo) {
    hi = __uint_as_float(cvt_tf32(x));
    lo = __uint_as_float(cvt_tf32(x - hi));
}
__device__ __forceinline__ unsigned ordf(float f) {
    unsigned u = __float_as_uint(f);
    return (u & 0x80000000u) ? ~u : (u | 0x80000000u);
}
__device__ __forceinline__ u32 smem_u32(const void* p) {
    u32 a;
    asm("{ .reg .u64 t; cvta.to.shared.u64 t, %1; cvt.u32.u64 %0, t; }" : "=r"(a) : "l"(p));
    return a;
}
__device__ __forceinline__ void cp16(u32 dst, const void* src) {
    asm volatile("cp.async.cg.shared.global [%0], [%1], 16;" :: "r"(dst), "l"(src));
}
#define CP_COMMIT() asm volatile("cp.async.commit_group;" ::: "memory")
#define CP_WAIT(n)  asm volatile("cp.async.wait_group %0;" :: "n"(n) : "memory")

__device__ __forceinline__ void mma_tf32(float* c, const u32* a, const u32* b) {
    asm volatile(
        "mma.sync.aligned.m16n8k8.row.col.f32.tf32.tf32.f32 "
        "{%0,%1,%2,%3}, {%4,%5,%6,%7}, {%8,%9}, {%0,%1,%2,%3};"
        : "+f"(c[0]), "+f"(c[1]), "+f"(c[2]), "+f"(c[3])
        : "r"(a[0]), "r"(a[1]), "r"(a[2]), "r"(a[3]), "r"(b[0]), "r"(b[1]));
}

// ---------------- pre-split kernels ----------------
__global__ void split_z(const float* __restrict__ z) {
    int idx = blockIdx.x * 256 + threadIdx.x;          // < 4,194,304
    int mtile = idx >> 10, rem = idx & 1023;
    int ks = rem >> 5, lane = rem & 31;
    int g = lane >> 2, c = lane & 3;
    int m0 = mtile * 16 + g, k0 = ks * 8 + c;
    float v0 = z[(size_t)m0 * 256 + k0];
    float v1 = z[(size_t)(m0 + 8) * 256 + k0];
    float v2 = z[(size_t)m0 * 256 + k0 + 4];
    float v3 = z[(size_t)(m0 + 8) * 256 + k0 + 4];
    float4 hi, lo;
    split1(v0, hi.x, lo.x); split1(v1, hi.y, lo.y);
    split1(v2, hi.z, lo.z); split1(v3, hi.w, lo.w);
    *(float4*)&g_zh[(size_t)idx * 4] = hi;
    *(float4*)&g_zl[(size_t)idx * 4] = lo;
}

__global__ void split_e(const float* __restrict__ emb) {
    int idx = blockIdx.x * 256 + threadIdx.x;          // < 131,072
    int ks = idx >> 12, rem = idx & 4095;
    int nt = rem >> 5, lane = rem & 31;
    int g = lane >> 2, c = lane & 3;
    int n = nt * 8 + g, k0 = ks * 8 + c;
    float v0 = emb[(size_t)n * 256 + k0];
    float v1 = emb[(size_t)n * 256 + k0 + 4];
    float2 hi, lo;
    split1(v0, hi.x, lo.x); split1(v1, hi.y, lo.y);
    *(float2*)&g_eh[(size_t)idx * 2] = hi;
    *(float2*)&g_el[(size_t)idx * 2] = lo;
}

__global__ void e2_kernel(const float* __restrict__ emb) {
    int w = (blockIdx.x * blockDim.x + threadIdx.x) >> 5;
    int lane = threadIdx.x & 31;
    if (w >= N_EMBED) return;
    const float* row = emb + (size_t)w * EMBED_DIM;
    float s = 0.f;
    #pragma unroll
    for (int k = 0; k < EMBED_DIM / 32; k++) {
        float v = row[lane + k * 32];
        s = fmaf(v, v, s);
    }
    #pragma unroll
    for (int off = 16; off; off >>= 1) s += __shfl_xor_sync(0xffffffffu, s, off);
    if (lane == 0) g_e2[w] = s;
}

// ---------------- main kernel: 512 thr, MTILE=128, warp tile 32x32 ----------------
__global__ void __launch_bounds__(512, 1)
vq_mma(const float* __restrict__ emb, float* __restrict__ out) {
    extern __shared__ char sm[];
    const u32 sbase = smem_u32(sm);
    const int tid = threadIdx.x;
    const int wid = tid >> 5;
    const int lane = tid & 31;
    const int warp_m = wid & 3;       // 0..3 (32 rows each)
    const int warp_n = wid >> 2;      // 0..3 (32 cols each)
    const int g = lane >> 2, cquad = lane & 3;
    const int row_base = blockIdx.x * MTILE;
    const int rb16 = blockIdx.x * 8;  // base mtile (8 mtiles of 16 rows)

    float* e2_s = (float*)(sm + E2_OFF);
    for (int i = tid; i < N_EMBED; i += 512) e2_s[i] = g_e2[i];

    // staging: stage = (nc, kc), KCHUNK=32 (4 ksteps)
    auto issue_copy = [&](int st, int buf) {
        const int nc = st >> 3, kc = st & 7;
        // A: 1024 chunks/half (mt 8 x ks 4 x pos 32) -> 2 per thread per half
        #pragma unroll
        for (int i = 0; i < 2; i++) {
            int cch = tid + i * 512;
            int mt = cch >> 7, ks = (cch >> 5) & 3, pos = cch & 31;
            size_t gsrc = ((size_t)(rb16 + mt) * 32 + kc * 4 + ks) * 128 + pos * 4;
            u32 doff = (u32)((ks * 8 + mt) * 512 + pos * 16);
            cp16(sbase + AH_OFF(buf) + doff, g_zh + gsrc);
            cp16(sbase + AL_OFF(buf) + doff, g_zl + gsrc);
        }
        // B: 1024 chunks/half (ks 4 x nt 16 x pos 16) -> 2 per thread per half
        #pragma unroll
        for (int i = 0; i < 2; i++) {
            int cch = tid + i * 512;
            int ks = cch >> 8, nt = (cch >> 4) & 15, pos = cch & 15;
            size_t gsrc = ((size_t)(kc * 4 + ks) * 128 + nc * 16 + nt) * 64 + pos * 4;
            u32 doff = (u32)((ks * 16 + nt) * 256 + pos * 16);
            cp16(sbase + BH_OFF(buf) + doff, g_eh + gsrc);
            cp16(sbase + BL_OFF(buf) + doff, g_el + gsrc);
        }
    };

    float bestd[4];
    int   bestn[4];
    #pragma unroll
    for (int i = 0; i < 4; i++) { bestd[i] = __int_as_float(0x7f800000); bestn[i] = 0; }

    float acc[2][4][4];   // [m-half][n8-tile][quad] = 32 regs

    issue_copy(0, 0); CP_COMMIT();
    issue_copy(1, 1); CP_COMMIT();

    for (int st = 0; st < 64; st++) {
        const int nc = st >> 3, kc = st & 7;
        const int buf = st % 3;
        if (kc == 0) {
            #pragma unroll
            for (int t = 0; t < 2; t++)
                #pragma unroll
                for (int j = 0; j < 4; j++)
                    #pragma unroll
                    for (int q = 0; q < 4; q++) acc[t][j][q] = 0.f;
        }
        if (st < 63) { CP_WAIT(1); } else { CP_WAIT(0); }
        __syncthreads();
        if (st + 2 < 64) { issue_copy(st + 2, (st + 2) % 3); CP_COMMIT(); }

        // ---- 4 ksteps of 3xTF32 MMAs (low reg pressure -> compiler pipelines) ----
        #pragma unroll
        for (int s = 0; s < 4; s++) {
            u32 ah[2][4], al[2][4];
            #pragma unroll
            for (int t = 0; t < 2; t++) {
                u32 aoff = (u32)((s * 8 + warp_m * 2 + t) * 512 + lane * 16);
                *(uint4*)ah[t] = *(const uint4*)(sm + AH_OFF(buf) + aoff);
                *(uint4*)al[t] = *(const uint4*)(sm + AL_OFF(buf) + aoff);
            }
            u32 bh[4][2], bl[4][2];
            #pragma unroll
            for (int j = 0; j < 4; j++) {
                u32 boff = (u32)((s * 16 + warp_n * 4 + j) * 256 + lane * 8);
                *(uint2*)bh[j] = *(const uint2*)(sm + BH_OFF(buf) + boff);
                *(uint2*)bl[j] = *(const uint2*)(sm + BL_OFF(buf) + boff);
            }
            #pragma unroll
            for (int t = 0; t < 2; t++) {
                #pragma unroll
                for (int j = 0; j < 4; j++) {
                    float* c = acc[t][j];
                    mma_tf32(c, ah[t], bh[j]);
                    mma_tf32(c, ah[t], bl[j]);
                    mma_tf32(c, al[t], bh[j]);
                }
            }
        }

        // ---- fold finished n-chunk into per-thread argmin ----
        if (kc == 7) {
            #pragma unroll
            for (int t = 0; t < 2; t++) {
                #pragma unroll
                for (int j = 0; j < 4; j++) {
                    int n0 = nc * NCHUNK + warp_n * 32 + j * 8 + 2 * cquad;
                    float e20 = e2_s[n0], e21 = e2_s[n0 + 1];
                    float d00 = fmaf(-2.f, acc[t][j][0], e20);
                    float d01 = fmaf(-2.f, acc[t][j][1], e21);
                    float d10 = fmaf(-2.f, acc[t][j][2], e20);
                    float d11 = fmaf(-2.f, acc[t][j][3], e21);
                    int s0 = t * 2, s1 = t * 2 + 1;
                    if (d00 < bestd[s0]) { bestd[s0] = d00; bestn[s0] = n0; }
                    if (d01 < bestd[s0]) { bestd[s0] = d01; bestn[s0] = n0 + 1; }
                    if (d10 < bestd[s1]) { bestd[s1] = d10; bestn[s1] = n0; }
                    if (d11 < bestd[s1]) { bestd[s1] = d11; bestn[s1] = n0 + 1; }
                }
            }
        }
    }

    // ---- reduce over the 4 lanes of each quad (cols within thread-quad) ----
    u64 keys[4];
    #pragma unroll
    for (int i = 0; i < 4; i++)
        keys[i] = ((u64)ordf(bestd[i]) << 32) | (unsigned)bestn[i];
    #pragma unroll
    for (int off = 1; off < 4; off <<= 1) {
        #pragma unroll
        for (int i = 0; i < 4; i++) {
            u64 o = __shfl_xor_sync(0xffffffffu, keys[i], off);
            if (o < keys[i]) keys[i] = o;
        }
    }
    u64* key_s = (u64*)(sm + KEY_OFF);
    if (cquad == 0) {
        #pragma unroll
        for (int t = 0; t < 2; t++)
            #pragma unroll
            for (int rh = 0; rh < 2; rh++) {
                int row = warp_m * 32 + t * 16 + rh * 8 + g;
                key_s[row * 4 + warp_n] = keys[t * 2 + rh];
            }
    }
    __syncthreads();

    if (tid < 128) {
        u64 k0 = key_s[tid * 4], k1 = key_s[tid * 4 + 1];
        u64 k2 = key_s[tid * 4 + 2], k3 = key_s[tid * 4 + 3];
        u64 ka = (k1 < k0) ? k1 : k0;
        u64 kb = (k3 < k2) ? k3 : k2;
        u64 k = (kb < ka) ? kb : ka;
        key_s[tid * 4] = k;
        out[(size_t)ZQ_ELEMS + row_base + tid] = (float)(unsigned)(k & 0xffffffffull);
    }
    __syncthreads();

    // ---- z_q gather ----
    float4* outq = (float4*)out;
    for (int it = tid; it < 128 * 64; it += 512) {
        int r  = it >> 6;
        int c4 = it & 63;
        unsigned idx = (unsigned)(key_s[r * 4] & 0xffffffffull);
        float4 v = *(const float4*)(emb + (size_t)idx * EMBED_DIM + c4 * 4);
        outq[(size_t)(row_base + r) * 64 + c4] = v;
    }
}

extern "C" void kernel_launch(void* const* d_in, const int* in_sizes, int n_in,
                              void* d_out, int out_size) {
    const float* z   = (const float*)d_in[0];
    const float* emb = (const float*)d_in[1];
    float* out = (float*)d_out;

    split_z<<<16384, 256>>>(z);
    split_e<<<512, 256>>>(emb);
    e2_kernel<<<N_EMBED / 8, 256>>>(emb);

    cudaFuncSetAttribute(vq_mma, cudaFuncAttributeMaxDynamicSharedMemorySize, SMEM_TOTAL);
    vq_mma<<<N_ROWS / MTILE, 512, SMEM_TOTAL>>>(emb, out);
}

// round 17
// speedup vs baseline: 1.1037x; 1.1037x over previous
#include <cuda_runtime.h>
#include <cstdint>

typedef unsigned long long u64;
typedef unsigned int u32;

#define N_EMBED   1024
#define EMBED_DIM 256
#define N_ROWS    65536
#define MTILE     128
#define NCHUNK    128
#define ZQ_ELEMS  (N_ROWS * EMBED_DIM)
#define NTHREADS  320
#define NCONS     256

// ---- global scratch: fragment-major pre-split operands ----
__device__ float g_zh[16777216];
__device__ float g_zl[16777216];
__device__ float g_eh[262144];
__device__ float g_el[262144];
__device__ float g_e2[N_EMBED];

// ---- smem layout (bytes): 3-stage ring, 64KB/stage ----
#define STG(s)    ((s) * 65536)
#define AH_OFF(s) (STG(s) + 0)
#define AL_OFF(s) (STG(s) + 16384)
#define BH_OFF(s) (STG(s) + 32768)
#define BL_OFF(s) (STG(s) + 49152)
#define E2_OFF    196608
#define KEY_OFF   200704
#define MBAR_OFF  202752   /* full[3] @ +0,8,16 ; empty[3] @ +24,32,40 */
#define SMEM_TOTAL 204800

__device__ __forceinline__ u32 cvt_tf32(float x) {
    u32 r;
    asm("cvt.rna.tf32.f32 %0, %1;" : "=r"(r) : "f"(x));
    return r;
}
__device__ __forceinline__ void split1(float x, float& hi, float& lo) {
    hi = __uint_as_float(cvt_tf32(x));
    lo = __uint_as_float(cvt_tf32(x - hi));
}
__device__ __forceinline__ unsigned ordf(float f) {
    unsigned u = __float_as_uint(f);
    return (u & 0x80000000u) ? ~u : (u | 0x80000000u);
}
__device__ __forceinline__ u32 smem_u32(const void* p) {
    u32 a;
    asm("{ .reg .u64 t; cvta.to.shared.u64 t, %1; cvt.u32.u64 %0, t; }" : "=r"(a) : "l"(p));
    return a;
}
__device__ __forceinline__ void cp16(u32 dst, const void* src) {
    asm volatile("cp.async.cg.shared.global [%0], [%1], 16;" :: "r"(dst), "l"(src));
}
__device__ __forceinline__ void mbar_init(u32 a, u32 cnt) {
    asm volatile("mbarrier.init.shared.b64 [%0], %1;" :: "r"(a), "r"(cnt) : "memory");
}
__device__ __forceinline__ void mbar_arrive(u32 a) {
    asm volatile("mbarrier.arrive.shared.b64 _, [%0];" :: "r"(a) : "memory");
}
// .noinc: the async arrival COUNTS against the initialized expected count.
// (default form increments expected count first -> net zero -> deadlock, R16 bug)
__device__ __forceinline__ void cp_arrive_noinc(u32 a) {
    asm volatile("cp.async.mbarrier.arrive.noinc.shared.b64 [%0];" :: "r"(a) : "memory");
}
__device__ __forceinline__ void mbar_wait(u32 a, u32 parity) {
    asm volatile(
        "{\n\t.reg .pred P1;\n\t"
        "WL%=:\n\t"
        "mbarrier.try_wait.parity.shared.b64 P1, [%0], %1, 0x989680;\n\t"
        "@P1 bra WD%=;\n\t"
        "bra WL%=;\n\t"
        "WD%=:\n\t}"
        :: "r"(a), "r"(parity) : "memory");
}
__device__ __forceinline__ void mma_tf32(float* c, const u32* a, const u32* b) {
    asm volatile(
        "mma.sync.aligned.m16n8k8.row.col.f32.tf32.tf32.f32 "
        "{%0,%1,%2,%3}, {%4,%5,%6,%7}, {%8,%9}, {%0,%1,%2,%3};"
        : "+f"(c[0]), "+f"(c[1]), "+f"(c[2]), "+f"(c[3])
        : "r"(a[0]), "r"(a[1]), "r"(a[2]), "r"(a[3]), "r"(b[0]), "r"(b[1]));
}

// ---------------- pre-split kernels ----------------
__global__ void split_z(const float* __restrict__ z) {
    int idx = blockIdx.x * 256 + threadIdx.x;
    int mtile = idx >> 10, rem = idx & 1023;
    int ks = rem >> 5, lane = rem & 31;
    int g = lane >> 2, c = lane & 3;
    int m0 = mtile * 16 + g, k0 = ks * 8 + c;
    float v0 = z[(size_t)m0 * 256 + k0];
    float v1 = z[(size_t)(m0 + 8) * 256 + k0];
    float v2 = z[(size_t)m0 * 256 + k0 + 4];
    float v3 = z[(size_t)(m0 + 8) * 256 + k0 + 4];
    float4 hi, lo;
    split1(v0, hi.x, lo.x); split1(v1, hi.y, lo.y);
    split1(v2, hi.z, lo.z); split1(v3, hi.w, lo.w);
    *(float4*)&g_zh[(size_t)idx * 4] = hi;
    *(float4*)&g_zl[(size_t)idx * 4] = lo;
}

__global__ void split_e(const float* __restrict__ emb) {
    int idx = blockIdx.x * 256 + threadIdx.x;
    int ks = idx >> 12, rem = idx & 4095;
    int nt = rem >> 5, lane = rem & 31;
    int g = lane >> 2, c = lane & 3;
    int n = nt * 8 + g, k0 = ks * 8 + c;
    float v0 = emb[(size_t)n * 256 + k0];
    float v1 = emb[(size_t)n * 256 + k0 + 4];
    float2 hi, lo;
    split1(v0, hi.x, lo.x); split1(v1, hi.y, lo.y);
    *(float2*)&g_eh[(size_t)idx * 2] = hi;
    *(float2*)&g_el[(size_t)idx * 2] = lo;
}

__global__ void e2_kernel(const float* __restrict__ emb) {
    int w = (blockIdx.x * blockDim.x + threadIdx.x) >> 5;
    int lane = threadIdx.x & 31;
    if (w >= N_EMBED) return;
    const float* row = emb + (size_t)w * EMBED_DIM;
    float s = 0.f;
    #pragma unroll
    for (int k = 0; k < EMBED_DIM / 32; k++) {
        float v = row[lane + k * 32];
        s = fmaf(v, v, s);
    }
    #pragma unroll
    for (int off = 16; off; off >>= 1) s += __shfl_xor_sync(0xffffffffu, s, off);
    if (lane == 0) g_e2[w] = s;
}

// ---------------- main kernel: warp-specialized producer/consumer ----------------
__global__ void __launch_bounds__(NTHREADS, 1)
vq_mma(const float* __restrict__ emb, float* __restrict__ out) {
    extern __shared__ char sm[];
    const u32 sbase = smem_u32(sm);
    const int tid = threadIdx.x;
    const int wid = tid >> 5;
    const int lane = tid & 31;
    const int row_base = blockIdx.x * MTILE;
    const int rb16 = blockIdx.x * 8;

    if (tid == 0) {
        #pragma unroll
        for (int b = 0; b < 3; b++) {
            mbar_init(sbase + MBAR_OFF + b * 8, 64);       // full: 64 producer threads (noinc async arrivals)
            mbar_init(sbase + MBAR_OFF + 24 + b * 8, 8);   // empty: 8 consumer warps
        }
    }
    float* e2_s = (float*)(sm + E2_OFF);
    for (int i = tid; i < N_EMBED; i += NTHREADS) e2_s[i] = g_e2[i];
    __syncthreads();

    u64* key_s = (u64*)(sm + KEY_OFF);

    if (wid >= 8) {
        // ================= PRODUCER (2 warps) =================
        const int ptid = tid - NCONS;   // 0..63
        int buf = 0, cyc = 0;
        for (int st = 0; st < 64; st++) {
            const int nc = st >> 3, kc = st & 7;
            if (cyc > 0) mbar_wait(sbase + MBAR_OFF + 24 + buf * 8, (cyc - 1) & 1);
            // A: 1024 chunks per half
            #pragma unroll
            for (int i = 0; i < 16; i++) {
                int cch = ptid + i * 64;
                int mt = cch >> 7, ks = (cch >> 5) & 3, pos = cch & 31;
                size_t gsrc = ((size_t)(rb16 + mt) * 32 + kc * 4 + ks) * 128 + pos * 4;
                u32 doff = (u32)((ks * 8 + mt) * 512 + pos * 16);
                cp16(sbase + AH_OFF(buf) + doff, g_zh + gsrc);
                cp16(sbase + AL_OFF(buf) + doff, g_zl + gsrc);
            }
            // B: 1024 chunks per half
            #pragma unroll
            for (int i = 0; i < 16; i++) {
                int cch = ptid + i * 64;
                int ks = cch >> 8, nt = (cch >> 4) & 15, pos = cch & 15;
                size_t gsrc = ((size_t)(kc * 4 + ks) * 128 + nc * 16 + nt) * 64 + pos * 4;
                u32 doff = (u32)((ks * 16 + nt) * 256 + pos * 16);
                cp16(sbase + BH_OFF(buf) + doff, g_eh + gsrc);
                cp16(sbase + BL_OFF(buf) + doff, g_el + gsrc);
            }
            cp_arrive_noinc(sbase + MBAR_OFF + buf * 8);
            if (++buf == 3) { buf = 0; cyc++; }
        }
    } else {
        // ================= CONSUMER (8 warps) =================
        const int warp_m = wid >> 1;      // 0..3 (32 rows)
        const int warp_n = wid & 1;       // 0..1 (64 cols)
        const int g = lane >> 2, cquad = lane & 3;

        float bestd[4];
        int   bestn[4];
        #pragma unroll
        for (int i = 0; i < 4; i++) { bestd[i] = __int_as_float(0x7f800000); bestn[i] = 0; }

        float acc[2][8][4];
        int buf = 0, cyc = 0;

        for (int st = 0; st < 64; st++) {
            const int nc = st >> 3, kc = st & 7;
            if (kc == 0) {
                #pragma unroll
                for (int t = 0; t < 2; t++)
                    #pragma unroll
                    for (int j = 0; j < 8; j++)
                        #pragma unroll
                        for (int q = 0; q < 4; q++) acc[t][j][q] = 0.f;
            }
            mbar_wait(sbase + MBAR_OFF + buf * 8, cyc & 1);

            // ---- 4 ksteps of 3xTF32 MMAs ----
            #pragma unroll
            for (int s = 0; s < 4; s++) {
                u32 ah[2][4], al[2][4];
                #pragma unroll
                for (int t = 0; t < 2; t++) {
                    u32 aoff = (u32)((s * 8 + warp_m * 2 + t) * 512 + lane * 16);
                    *(uint4*)ah[t] = *(const uint4*)(sm + AH_OFF(buf) + aoff);
                    *(uint4*)al[t] = *(const uint4*)(sm + AL_OFF(buf) + aoff);
                }
                u32 bh[8][2], bl[8][2];
                #pragma unroll
                for (int j = 0; j < 8; j++) {
                    u32 boff = (u32)((s * 16 + warp_n * 8 + j) * 256 + lane * 8);
                    *(uint2*)bh[j] = *(const uint2*)(sm + BH_OFF(buf) + boff);
                    *(uint2*)bl[j] = *(const uint2*)(sm + BL_OFF(buf) + boff);
                }
                #pragma unroll
                for (int t = 0; t < 2; t++) {
                    #pragma unroll
                    for (int j = 0; j < 8; j++) {
                        float* c = acc[t][j];
                        mma_tf32(c, ah[t], bh[j]);
                        mma_tf32(c, ah[t], bl[j]);
                        mma_tf32(c, al[t], bh[j]);
                    }
                }
            }
            if (lane == 0) mbar_arrive(sbase + MBAR_OFF + 24 + buf * 8);

            // ---- fold finished n-chunk ----
            if (kc == 7) {
                #pragma unroll
                for (int t = 0; t < 2; t++) {
                    #pragma unroll
                    for (int j = 0; j < 8; j++) {
                        int n0 = nc * NCHUNK + warp_n * 64 + j * 8 + 2 * cquad;
                        float e20 = e2_s[n0], e21 = e2_s[n0 + 1];
                        float d00 = fmaf(-2.f, acc[t][j][0], e20);
                        float d01 = fmaf(-2.f, acc[t][j][1], e21);
                        float d10 = fmaf(-2.f, acc[t][j][2], e20);
                        float d11 = fmaf(-2.f, acc[t][j][3], e21);
                        int s0 = t * 2, s1 = t * 2 + 1;
                        if (d00 < bestd[s0]) { bestd[s0] = d00; bestn[s0] = n0; }
                        if (d01 < bestd[s0]) { bestd[s0] = d01; bestn[s0] = n0 + 1; }
                        if (d10 < bestd[s1]) { bestd[s1] = d10; bestn[s1] = n0; }
                        if (d11 < bestd[s1]) { bestd[s1] = d11; bestn[s1] = n0 + 1; }
                    }
                }
            }
            if (++buf == 3) { buf = 0; cyc++; }
        }

        // ---- reduce over the 4 lanes of each quad ----
        u64 keys[4];
        #pragma unroll
        for (int i = 0; i < 4; i++)
            keys[i] = ((u64)ordf(bestd[i]) << 32) | (unsigned)bestn[i];
        #pragma unroll
        for (int off = 1; off < 4; off <<= 1) {
            #pragma unroll
            for (int i = 0; i < 4; i++) {
                u64 o = __shfl_xor_sync(0xffffffffu, keys[i], off);
                if (o < keys[i]) keys[i] = o;
            }
        }
        if (cquad == 0) {
            #pragma unroll
            for (int t = 0; t < 2; t++)
                #pragma unroll
                for (int rh = 0; rh < 2; rh++) {
                    int row = warp_m * 32 + t * 16 + rh * 8 + g;
                    key_s[row * 2 + warp_n] = keys[t * 2 + rh];
                }
        }
    }

    __syncthreads();
    if (tid < 128) {
        u64 k0 = key_s[tid * 2], k1 = key_s[tid * 2 + 1];
        u64 k = (k1 < k0) ? k1 : k0;
        key_s[tid * 2] = k;
        out[(size_t)ZQ_ELEMS + row_base + tid] = (float)(unsigned)(k & 0xffffffffull);
    }
    __syncthreads();

    // ---- z_q gather (all 320 threads) ----
    float4* outq = (float4*)out;
    for (int it = tid; it < 128 * 64; it += NTHREADS) {
        int r  = it >> 6;
        int c4 = it & 63;
        unsigned idx = (unsigned)(key_s[r * 2] & 0xffffffffull);
        float4 v = *(const float4*)(emb + (size_t)idx * EMBED_DIM + c4 * 4);
        outq[(size_t)(row_base + r) * 64 + c4] = v;
    }
}

extern "C" void kernel_launch(void* const* d_in, const int* in_sizes, int n_in,
                              void* d_out, int out_size) {
    const float* z   = (const float*)d_in[0];
    const float* emb = (const float*)d_in[1];
    float* out = (float*)d_out;

    split_z<<<16384, 256>>>(z);
    split_e<<<512, 256>>>(emb);
    e2_kernel<<<N_EMBED / 8, 256>>>(emb);

    cudaFuncSetAttribute(vq_mma, cudaFuncAttributeMaxDynamicSharedMemorySize, SMEM_TOTAL);
    vq_mma<<<N_ROWS / MTILE, NTHREADS, SMEM_TOTAL>>>(emb, out);
}